// round 3
// baseline (speedup 1.0000x reference)
#include <cuda_runtime.h>

#define BSZ 512
#define NN 1000
#define D 128
#define STR 384   // K_att/V_att innermost stride in floats (3 layers * 128)

__device__ __forceinline__ float4 zero4() { return make_float4(0.f, 0.f, 0.f, 0.f); }

// One CTA per batch. 256 threads = 8 warps.
// Warp w owns compacted positions w, w+8, w+16, ... processed in chunks of 2
// with one-chunk-ahead prefetch (>=2KB in flight per warp in the K+V loops).

__global__ __launch_bounds__(256, 4)
void decoder_fused_kernel(
    const float* __restrict__ query,
    const float* __restrict__ K_att,
    const float* __restrict__ V_att,
    const int* __restrict__ mask,          // bool serialized as int32
    const float* __restrict__ W0_w,
    const float* __restrict__ W0_b,
    const float* __restrict__ Wq_w,
    const float* __restrict__ Wq_b,
    float* __restrict__ out)
{
    __shared__ int nlist[NN];
    __shared__ int cnt_s;
    __shared__ __align__(16) float qs[D];   // current query
    __shared__ __align__(16) float mo[D];   // mha output / q_final
    __shared__ float m_s[8][32];
    __shared__ float l_s[8][32];
    __shared__ __align__(16) float4 a_s[8][32];
    __shared__ float M2s, L2s;

    const int b = blockIdx.x;
    const int tid = threadIdx.x;
    const int wid = tid >> 5;
    const int lane = tid & 31;
    const float NEG = __int_as_float(0xff800000);  // -inf

    if (tid < D) qs[tid] = query[(size_t)b * D + tid];

    // ---- Compact unmasked node list (deterministic order, warp 0) ----
    const int* mrow = mask + (size_t)b * NN;
    if (wid == 0) {
        int base = 0;
        for (int start = 0; start < NN; start += 32) {
            int n = start + lane;
            bool keep = (n < NN) && (mrow[n] == 0);
            unsigned bal = __ballot_sync(0xffffffffu, keep);
            if (keep) {
                int pos = base + __popc(bal & ((1u << lane) - 1u));
                nlist[pos] = n;
            }
            base += __popc(bal);
        }
        if (lane == 0) cnt_s = base;
    }
    __syncthreads();
    const int cnt = cnt_s;

    const float* Kb = K_att + (size_t)b * NN * STR;
    const float* Vb = V_att + (size_t)b * NN * STR;

    // ==================== Layers 0 and 1: 8-head MHA + W0 linear ====================
    for (int l = 0; l < 2; ++l) {
        const int coff = l * D + 4 * lane;
        const float4 q4 = *(const float4*)(qs + 4 * lane);

        float m = -1e30f, lsum = 0.0f;
        float4 acc = zero4();

        int p = wid;
        float4 k0, k1, v0, v1;
        {
            if (p < cnt) {
                size_t o = (size_t)nlist[p] * STR + coff;
                k0 = *(const float4*)(Kb + o); v0 = *(const float4*)(Vb + o);
            } else { k0 = zero4(); v0 = zero4(); }
            if (p + 8 < cnt) {
                size_t o = (size_t)nlist[p + 8] * STR + coff;
                k1 = *(const float4*)(Kb + o); v1 = *(const float4*)(Vb + o);
            } else { k1 = zero4(); v1 = zero4(); }
        }

        while (p < cnt) {
            const int pn = p + 16;
            // ---- prefetch next chunk (4 independent LDG.128 issued up front) ----
            float4 nk0, nk1, nv0, nv1;
            if (pn < cnt) {
                size_t o = (size_t)nlist[pn] * STR + coff;
                nk0 = *(const float4*)(Kb + o); nv0 = *(const float4*)(Vb + o);
            } else { nk0 = zero4(); nv0 = zero4(); }
            if (pn + 8 < cnt) {
                size_t o = (size_t)nlist[pn + 8] * STR + coff;
                nk1 = *(const float4*)(Kb + o); nv1 = *(const float4*)(Vb + o);
            } else { nk1 = zero4(); nv1 = zero4(); }

            // ---- compute current chunk: positions p (always valid), p+8 ----
            float s0 = k0.x * q4.x + k0.y * q4.y + k0.z * q4.z + k0.w * q4.w;
            float s1 = k1.x * q4.x + k1.y * q4.y + k1.z * q4.z + k1.w * q4.w;
            s0 += __shfl_xor_sync(0xffffffffu, s0, 1);
            s1 += __shfl_xor_sync(0xffffffffu, s1, 1);
            s0 += __shfl_xor_sync(0xffffffffu, s0, 2);
            s1 += __shfl_xor_sync(0xffffffffu, s1, 2);
            s0 *= 0.25f;                       // 1/sqrt(16)
            s1 = (p + 8 < cnt) ? s1 * 0.25f : NEG;

            float mn = fmaxf(m, s0);
            float c = __expf(m - mn);
            float e = __expf(s0 - mn);
            lsum = lsum * c + e;
            acc.x = acc.x * c + e * v0.x;
            acc.y = acc.y * c + e * v0.y;
            acc.z = acc.z * c + e * v0.z;
            acc.w = acc.w * c + e * v0.w;
            m = mn;

            mn = fmaxf(m, s1);
            c = __expf(m - mn);
            e = __expf(s1 - mn);               // s1 = -inf -> e = 0 (no-op)
            lsum = lsum * c + e;
            acc.x = acc.x * c + e * v1.x;
            acc.y = acc.y * c + e * v1.y;
            acc.z = acc.z * c + e * v1.z;
            acc.w = acc.w * c + e * v1.w;
            m = mn;

            k0 = nk0; k1 = nk1; v0 = nv0; v1 = nv1;
            p = pn;
        }

        m_s[wid][lane] = m;
        l_s[wid][lane] = lsum;
        a_s[wid][lane] = acc;
        __syncthreads();

        // merge the 8 warp-partials (lane t of warp 0 merges slot t)
        if (tid < 32) {
            float M = m_s[0][lane];
            #pragma unroll
            for (int w = 1; w < 8; ++w) M = fmaxf(M, m_s[w][lane]);
            float L = 0.f;
            float ax = 0.f, ay = 0.f, az = 0.f, aw = 0.f;
            #pragma unroll
            for (int w = 0; w < 8; ++w) {
                const float c = __expf(m_s[w][lane] - M);
                L += l_s[w][lane] * c;
                const float4 a = a_s[w][lane];
                ax += a.x * c; ay += a.y * c; az += a.z * c; aw += a.w * c;
            }
            const float inv = 1.0f / L;
            mo[4 * lane + 0] = ax * inv;
            mo[4 * lane + 1] = ay * inv;
            mo[4 * lane + 2] = az * inv;
            mo[4 * lane + 3] = aw * inv;
        }
        __syncthreads();

        // query = mha_out @ W0_w.T + W0_b
        if (tid < D) {
            const float* Wr = W0_w + tid * D;
            float a2 = W0_b[tid];
            #pragma unroll 8
            for (int d = 0; d < D; ++d) a2 = fmaf(mo[d], Wr[d], a2);
            qs[tid] = a2;
        }
        __syncthreads();
    }

    // ==================== Layer 2: q_final = q @ Wq.T + b; 1-head, clip=10 ====================
    if (tid < D) {
        const float* Wr = Wq_w + tid * D;
        float a2 = Wq_b[tid];
        #pragma unroll 8
        for (int d = 0; d < D; ++d) a2 = fmaf(qs[d], Wr[d], a2);
        mo[tid] = a2;
    }
    __syncthreads();

    {
        const float4 q4 = *(const float4*)(mo + 4 * lane);
        const int coff = 2 * D + 4 * lane;
        float* orow = out + (size_t)b * NN;

        float m = -1e30f, lsum = 0.0f;

        int p = wid;
        float4 k0, k1;
        int n0 = 0, n1 = 0;
        {
            if (p < cnt) {
                n0 = nlist[p];
                k0 = *(const float4*)(Kb + (size_t)n0 * STR + coff);
            } else k0 = zero4();
            if (p + 8 < cnt) {
                n1 = nlist[p + 8];
                k1 = *(const float4*)(Kb + (size_t)n1 * STR + coff);
            } else k1 = zero4();
        }

        while (p < cnt) {
            const int pn = p + 16;
            float4 nk0, nk1;
            int nn0 = 0, nn1 = 0;
            if (pn < cnt) {
                nn0 = nlist[pn];
                nk0 = *(const float4*)(Kb + (size_t)nn0 * STR + coff);
            } else nk0 = zero4();
            if (pn + 8 < cnt) {
                nn1 = nlist[pn + 8];
                nk1 = *(const float4*)(Kb + (size_t)nn1 * STR + coff);
            } else nk1 = zero4();

            float s0 = k0.x * q4.x + k0.y * q4.y + k0.z * q4.z + k0.w * q4.w;
            float s1 = k1.x * q4.x + k1.y * q4.y + k1.z * q4.z + k1.w * q4.w;
            #pragma unroll
            for (int d = 1; d < 32; d <<= 1) {
                s0 += __shfl_xor_sync(0xffffffffu, s0, d);
                s1 += __shfl_xor_sync(0xffffffffu, s1, d);
            }
            s0 *= 0.08838834764831845f;        // 1/sqrt(128)
            s1 *= 0.08838834764831845f;
            // clip: 10*tanh(s) = 10*(1 - 2/(exp(2s)+1))
            s0 = 10.0f * (1.0f - __fdividef(2.0f, __expf(2.0f * s0) + 1.0f));
            s1 = 10.0f * (1.0f - __fdividef(2.0f, __expf(2.0f * s1) + 1.0f));

            // slot 0 always valid (p < cnt)
            if (lane == 0) orow[n0] = s0;
            float mn = fmaxf(m, s0);
            lsum = lsum * __expf(m - mn) + __expf(s0 - mn);
            m = mn;

            const bool v1ok = (p + 8 < cnt);
            if (v1ok) {
                if (lane == 0) orow[n1] = s1;
            } else s1 = NEG;
            mn = fmaxf(m, s1);
            lsum = lsum * __expf(m - mn) + __expf(s1 - mn);
            m = mn;

            k0 = nk0; k1 = nk1; n0 = nn0; n1 = nn1;
            p = pn;
        }

        if (lane == 0) { m_s[wid][0] = m; l_s[wid][0] = lsum; }
        __syncthreads();
        if (tid == 0) {
            float M = m_s[0][0];
            #pragma unroll
            for (int w = 1; w < 8; ++w) M = fmaxf(M, m_s[w][0]);
            float L = 0.f;
            #pragma unroll
            for (int w = 0; w < 8; ++w) L += l_s[w][0] * __expf(m_s[w][0] - M);
            M2s = M;
            L2s = 1.0f / L;
        }
        __syncthreads();

        const float M = M2s, Li = L2s;
        for (int n = tid; n < NN; n += 256) {
            float v = 0.0f;
            if (mrow[n] == 0) v = __expf(orow[n] - M) * Li;
            orow[n] = v;
        }
    }
}

extern "C" void kernel_launch(void* const* d_in, const int* in_sizes, int n_in,
                              void* d_out, int out_size) {
    const float* query = (const float*)d_in[0];
    const float* K_att = (const float*)d_in[1];
    const float* V_att = (const float*)d_in[2];
    const int*   mask  = (const int*)d_in[3];
    const float* W0_w  = (const float*)d_in[4];
    const float* W0_b  = (const float*)d_in[5];
    const float* Wq_w  = (const float*)d_in[6];
    const float* Wq_b  = (const float*)d_in[7];
    float* out = (float*)d_out;

    decoder_fused_kernel<<<BSZ, 256>>>(query, K_att, V_att, mask,
                                       W0_w, W0_b, Wq_w, Wq_b, out);
}

// round 4
// speedup vs baseline: 1.0508x; 1.0508x over previous
#include <cuda_runtime.h>
#include <cuda_pipeline.h>

#define BSZ 512
#define NN 1000
#define D 128
#define STR 384   // K_att/V_att innermost stride in floats (3 layers * 128)
#define S 4       // pipeline depth in nodes (K+V layers); layer 2 uses 2*S

__device__ __forceinline__ float4 zero4() { return make_float4(0.f, 0.f, 0.f, 0.f); }

// One CTA per batch. 256 threads = 8 warps. Warp w owns compacted positions
// w, w+8, w+16, ... Each node's 512B row slice is staged into a per-warp smem
// ring via cp.async; lane t copies/reads only its own 16B [4t,4t+4).

__global__ __launch_bounds__(256, 4)
void decoder_fused_kernel(
    const float* __restrict__ query,
    const float* __restrict__ K_att,
    const float* __restrict__ V_att,
    const int* __restrict__ mask,          // bool serialized as int32
    const float* __restrict__ W0_w,
    const float* __restrict__ W0_b,
    const float* __restrict__ Wq_w,
    const float* __restrict__ Wq_b,
    float* __restrict__ out)
{
    __shared__ int nlist[NN];
    __shared__ int cnt_s;
    __shared__ __align__(16) float kst[8][S][D];   // 16 KB
    __shared__ __align__(16) float vst[8][S][D];   // 16 KB
    __shared__ __align__(16) float qs[D];
    __shared__ __align__(16) float mo[D];
    __shared__ float m_s[8][32];
    __shared__ float l_s[8][32];
    __shared__ __align__(16) float4 a_s[8][32];
    __shared__ float M2s, L2s;

    const int b = blockIdx.x;
    const int tid = threadIdx.x;
    const int wid = tid >> 5;
    const int lane = tid & 31;

    if (tid < D) qs[tid] = query[(size_t)b * D + tid];

    // ---- Compact unmasked node list (warp 0) ----
    const int* mrow = mask + (size_t)b * NN;
    if (wid == 0) {
        int base = 0;
        for (int start = 0; start < NN; start += 32) {
            int n = start + lane;
            bool keep = (n < NN) && (mrow[n] == 0);
            unsigned bal = __ballot_sync(0xffffffffu, keep);
            if (keep) {
                int pos = base + __popc(bal & ((1u << lane) - 1u));
                nlist[pos] = n;
            }
            base += __popc(bal);
        }
        if (lane == 0) cnt_s = base;
    }
    __syncthreads();
    const int cnt = cnt_s;

    const float* Kb = K_att + (size_t)b * NN * STR;
    const float* Vb = V_att + (size_t)b * NN * STR;

    float* kw = &kst[wid][0][0];
    float* vw = &vst[wid][0][0];
    const int loff = 4 * lane;

    // ==================== Layers 0 and 1: 8-head MHA + W0 linear ====================
    for (int l = 0; l < 2; ++l) {
        const int cbase = l * D + loff;

        // prologue: fill S stages
        #pragma unroll
        for (int s = 0; s < S; ++s) {
            int pos = wid + s * 8;
            if (pos < cnt) {
                size_t o = (size_t)nlist[pos] * STR + cbase;
                __pipeline_memcpy_async(kw + s * D + loff, Kb + o, 16);
                __pipeline_memcpy_async(vw + s * D + loff, Vb + o, 16);
            }
            __pipeline_commit();
        }

        const float4 q4 = *(const float4*)(qs + loff);
        float m = -1e30f, lsum = 0.0f;
        float4 acc = zero4();

        int p = wid, st = 0, pi = wid + S * 8;
        while (p < cnt) {
            __pipeline_wait_prior(S - 1);
            const float4 k4 = *(const float4*)(kw + st * D + loff);
            const float4 v4 = *(const float4*)(vw + st * D + loff);
            // refill this slot (write lands >= DRAM latency after the LDS above)
            if (pi < cnt) {
                size_t o = (size_t)nlist[pi] * STR + cbase;
                __pipeline_memcpy_async(kw + st * D + loff, Kb + o, 16);
                __pipeline_memcpy_async(vw + st * D + loff, Vb + o, 16);
            }
            __pipeline_commit();

            float s0 = k4.x * q4.x + k4.y * q4.y + k4.z * q4.z + k4.w * q4.w;
            s0 += __shfl_xor_sync(0xffffffffu, s0, 1);
            s0 += __shfl_xor_sync(0xffffffffu, s0, 2);
            s0 *= 0.25f;  // 1/sqrt(16)

            const float mn = fmaxf(m, s0);
            const float c = __expf(m - mn);
            const float e = __expf(s0 - mn);
            lsum = lsum * c + e;
            acc.x = acc.x * c + e * v4.x;
            acc.y = acc.y * c + e * v4.y;
            acc.z = acc.z * c + e * v4.z;
            acc.w = acc.w * c + e * v4.w;
            m = mn;

            st = (st + 1) & (S - 1);
            p += 8; pi += 8;
        }
        __pipeline_wait_prior(0);

        m_s[wid][lane] = m;
        l_s[wid][lane] = lsum;
        a_s[wid][lane] = acc;
        __syncthreads();

        // merge the 8 warp-partials (lane t of warp 0 merges slot t)
        if (tid < 32) {
            float M = m_s[0][lane];
            #pragma unroll
            for (int w = 1; w < 8; ++w) M = fmaxf(M, m_s[w][lane]);
            float L = 0.f;
            float ax = 0.f, ay = 0.f, az = 0.f, aw = 0.f;
            #pragma unroll
            for (int w = 0; w < 8; ++w) {
                const float c = __expf(m_s[w][lane] - M);
                L += l_s[w][lane] * c;
                const float4 a = a_s[w][lane];
                ax += a.x * c; ay += a.y * c; az += a.z * c; aw += a.w * c;
            }
            const float inv = 1.0f / L;
            mo[4 * lane + 0] = ax * inv;
            mo[4 * lane + 1] = ay * inv;
            mo[4 * lane + 2] = az * inv;
            mo[4 * lane + 3] = aw * inv;
        }
        __syncthreads();

        // query = mha_out @ W0_w.T + W0_b
        if (tid < D) {
            const float* Wr = W0_w + tid * D;
            float a2 = W0_b[tid];
            #pragma unroll 8
            for (int d = 0; d < D; ++d) a2 = fmaf(mo[d], Wr[d], a2);
            qs[tid] = a2;
        }
        __syncthreads();
    }

    // ==================== Layer 2: q_final = q @ Wq.T + b; 1-head, clip=10 ====================
    if (tid < D) {
        const float* Wr = Wq_w + tid * D;
        float a2 = Wq_b[tid];
        #pragma unroll 8
        for (int d = 0; d < D; ++d) a2 = fmaf(qs[d], Wr[d], a2);
        mo[tid] = a2;
    }
    __syncthreads();

    {
        const int cbase = 2 * D + loff;
        const float4 q4 = *(const float4*)(mo + loff);
        float* orow = out + (size_t)b * NN;

        // K-only: use both rings => depth 2*S = 8 nodes
        #pragma unroll
        for (int s = 0; s < 2 * S; ++s) {
            int pos = wid + s * 8;
            float* dst = (s < S ? kw + s * D : vw + (s - S) * D) + loff;
            if (pos < cnt)
                __pipeline_memcpy_async(dst, Kb + (size_t)nlist[pos] * STR + cbase, 16);
            __pipeline_commit();
        }

        float m = -1e30f, lsum = 0.0f;
        int p = wid, st = 0, pi = wid + 2 * S * 8;
        while (p < cnt) {
            __pipeline_wait_prior(2 * S - 1);
            float* slot = (st < S ? kw + st * D : vw + (st - S) * D) + loff;
            const float4 k4 = *(const float4*)slot;
            if (pi < cnt)
                __pipeline_memcpy_async(slot, Kb + (size_t)nlist[pi] * STR + cbase, 16);
            __pipeline_commit();

            float s0 = k4.x * q4.x + k4.y * q4.y + k4.z * q4.z + k4.w * q4.w;
            #pragma unroll
            for (int d = 1; d < 32; d <<= 1)
                s0 += __shfl_xor_sync(0xffffffffu, s0, d);
            s0 *= 0.08838834764831845f;  // 1/sqrt(128)
            // 10*tanh(s) = 10*(1 - 2/(exp(2s)+1))
            s0 = 10.0f * (1.0f - __fdividef(2.0f, __expf(2.0f * s0) + 1.0f));

            if (lane == 0) orow[nlist[p]] = s0;  // stage unnormalized logit
            const float mn = fmaxf(m, s0);
            lsum = lsum * __expf(m - mn) + __expf(s0 - mn);
            m = mn;

            st = (st + 1) & (2 * S - 1);
            p += 8; pi += 8;
        }
        __pipeline_wait_prior(0);

        if (lane == 0) { m_s[wid][0] = m; l_s[wid][0] = lsum; }
        __syncthreads();
        if (tid == 0) {
            float M = m_s[0][0];
            #pragma unroll
            for (int w = 1; w < 8; ++w) M = fmaxf(M, m_s[w][0]);
            float L = 0.f;
            #pragma unroll
            for (int w = 0; w < 8; ++w) L += l_s[w][0] * __expf(m_s[w][0] - M);
            M2s = M;
            L2s = 1.0f / L;
        }
        __syncthreads();

        const float M = M2s, Li = L2s;
        for (int n = tid; n < NN; n += 256) {
            float v = 0.0f;
            if (mrow[n] == 0) v = __expf(orow[n] - M) * Li;
            orow[n] = v;
        }
    }
}

extern "C" void kernel_launch(void* const* d_in, const int* in_sizes, int n_in,
                              void* d_out, int out_size) {
    const float* query = (const float*)d_in[0];
    const float* K_att = (const float*)d_in[1];
    const float* V_att = (const float*)d_in[2];
    const int*   mask  = (const int*)d_in[3];
    const float* W0_w  = (const float*)d_in[4];
    const float* W0_b  = (const float*)d_in[5];
    const float* Wq_w  = (const float*)d_in[6];
    const float* Wq_b  = (const float*)d_in[7];
    float* out = (float*)d_out;

    decoder_fused_kernel<<<BSZ, 256>>>(query, K_att, V_att, mask,
                                       W0_w, W0_b, Wq_w, Wq_b, out);
}